// round 6
// baseline (speedup 1.0000x reference)
#include <cuda_runtime.h>
#include <cstddef>

#define BATCH 16
#define NPTS  1024
#define KNN   20
#define BN    (BATCH*NPTS)

typedef unsigned long long ull;

// ---------------- scratch (static device globals; allocation-free) ----------------
__device__ float g_hA[BN*256];
__device__ float g_hB[BN*256];
__device__ float g_u [BN*256];
__device__ float g_w [BN*256];
__device__ float g_ymax[BN*256];
__device__ float g_ymin[BN*256];
__device__ float g_xx[BN];
__device__ float g_dist[BATCH*NPTS*NPTS];     // 67 MB, L2-resident
__device__ float g_nodemin[BN*128];           // per-row mins of 8-leaf groups
__device__ int   g_idx[BN*KNN];
__device__ float g_ps[256*1024];              // stats partials [o][block]
__device__ float g_pq[256*1024];
__device__ float g_scale[256];
__device__ float g_shift[256];
__device__ float g_part[BATCH*16*256];

// ---------------- f32x2 helpers ----------------
__device__ __forceinline__ void fma2(ull& d, ull a, ull b) {
    asm("fma.rn.f32x2 %0, %1, %2, %0;" : "+l"(d) : "l"(a), "l"(b));
}
__device__ __forceinline__ float2 upk(ull v) {
    float2 f; asm("mov.b64 {%0,%1}, %2;" : "=f"(f.x), "=f"(f.y) : "l"(v)); return f;
}
__device__ __forceinline__ unsigned redux_min_u32(unsigned v) {
    unsigned r; asm("redux.sync.min.u32 %0, %1, 0xffffffff;" : "=r"(r) : "r"(v)); return r;
}
__device__ __forceinline__ int redux_min_s32(int v) {
    int r; asm("redux.sync.min.s32 %0, %1, 0xffffffff;" : "=r"(r) : "r"(v)); return r;
}

// ---------------- prep: x (B,1,4,N) -> h (B,N,4) ----------------
__global__ void prep_kernel(const float* __restrict__ x, float* __restrict__ h) {
    int i = blockIdx.x*256 + threadIdx.x;          // over B*N*4
    int c = i & 3, n = (i >> 2) & (NPTS-1), b = i >> 12;
    h[i] = x[((size_t)b*4 + c)*NPTS + n];
}

// ---------------- xx[b,n] = |h_bn|^2 ----------------
template<int C>
__global__ void xx_kernel(const float* __restrict__ h, float* __restrict__ xx) {
    int i = blockIdx.x*256 + threadIdx.x;          // over B*N
    const float4* hp = (const float4*)(h + (size_t)i*C);
    float s = 0.f;
#pragma unroll
    for (int c = 0; c < C/4; c++) { float4 v = hp[c]; s += v.x*v.x + v.y*v.y + v.z*v.z + v.w*v.w; }
    xx[i] = s;
}

// ---------------- pairwise squared distances + per-group node mins ----------------
template<int C>
__global__ __launch_bounds__(256) void dist_kernel(const float* __restrict__ h,
                                                   const float* __restrict__ xx,
                                                   float* __restrict__ dist,
                                                   float* __restrict__ nodemin) {
    constexpr int KC = (C >= 8) ? 8 : 4;
    __shared__ float As[KC][264];   // 128 rows duplicated pairs (256 floats) + pad
    __shared__ float Bs[KC][136];   // 128 floats + pad
    __shared__ float Ts[64][66];    // transpose staging (float2-aligned dump)
    int bx = blockIdx.x, by = blockIdx.y, b = blockIdx.z;
    if (bx > by) return;            // symmetry: compute lower triangle, mirror
    int n0 = by * 128, m0 = bx * 128;
    int tid = threadIdx.x;
    int tx = tid & 15, ty = tid >> 4;   // 16x16 threads, 8x8 values each
    ull acc[8][4];
#pragma unroll
    for (int i = 0; i < 8; i++)
#pragma unroll
        for (int j = 0; j < 4; j++) acc[i][j] = 0ull;
    const float* hb = h + (size_t)b*NPTS*C;
    for (int kk = 0; kk < C; kk += KC) {
        for (int e = tid; e < 128*KC; e += 256) {
            int r = e / KC, c = e % KC;
            float va = hb[(size_t)(n0 + r)*C + kk + c];
            As[c][2*r] = va; As[c][2*r+1] = va;
            Bs[c][r] = hb[(size_t)(m0 + r)*C + kk + c];
        }
        __syncthreads();
#pragma unroll
        for (int c = 0; c < KC; c++) {
            const ull* ap = (const ull*)&As[c][ty*16];
            const ull* bp = (const ull*)&Bs[c][tx*8];
            ull A[8], B[4];
#pragma unroll
            for (int i = 0; i < 8; i++) A[i] = ap[i];
#pragma unroll
            for (int j = 0; j < 4; j++) B[j] = bp[j];
#pragma unroll
            for (int i = 0; i < 8; i++)
#pragma unroll
                for (int j = 0; j < 4; j++) fma2(acc[i][j], A[i], B[j]);
        }
        __syncthreads();
    }
    const float* xxb = xx + b*NPTS;
    float xn[8], xm[8];
#pragma unroll
    for (int i = 0; i < 8; i++) { xn[i] = xxb[n0+ty*8+i]; xm[i] = xxb[m0+tx*8+i]; }
    float ov[8][8];
#pragma unroll
    for (int i = 0; i < 8; i++)
#pragma unroll
        for (int j = 0; j < 4; j++) {
            float2 p = upk(acc[i][j]);
            ov[i][2*j]   = xn[i] + xm[2*j]   - 2.f*p.x;
            ov[i][2*j+1] = xn[i] + xm[2*j+1] - 2.f*p.y;
        }
    float* db = dist + (size_t)b*NPTS*NPTS;
    float* nmb = nodemin + (size_t)b*NPTS*128;
#pragma unroll
    for (int i = 0; i < 8; i++) {
        size_t off = (size_t)(n0+ty*8+i)*NPTS + m0 + tx*8;
        *(float4*)&db[off]   = make_float4(ov[i][0], ov[i][1], ov[i][2], ov[i][3]);
        *(float4*)&db[off+4] = make_float4(ov[i][4], ov[i][5], ov[i][6], ov[i][7]);
        // node min for row n0+ty*8+i, group bx*16+tx (cols m0+tx*8..+7)
        float m = fminf(fminf(fminf(ov[i][0],ov[i][1]), fminf(ov[i][2],ov[i][3])),
                        fminf(fminf(ov[i][4],ov[i][5]), fminf(ov[i][6],ov[i][7])));
        nmb[(size_t)(n0+ty*8+i)*128 + bx*16 + tx] = m;
    }
    if (bx == by) return;
    // mirror node mins: row m0+tx*8+j, group by*16+ty (cols n0+ty*8..+7)
#pragma unroll
    for (int j = 0; j < 8; j++) {
        float m = fminf(fminf(fminf(ov[0][j],ov[1][j]), fminf(ov[2][j],ov[3][j])),
                        fminf(fminf(ov[4][j],ov[5][j]), fminf(ov[6][j],ov[7][j])));
        nmb[(size_t)(m0+tx*8+j)*128 + by*16 + ty] = m;
    }
    // mirror dist: 4 sub-passes through a 64x64 smem transpose
#pragma unroll
    for (int sr = 0; sr < 2; sr++)
#pragma unroll
        for (int sc = 0; sc < 2; sc++) {
            __syncthreads();
            if ((ty >> 3) == sr && (tx >> 3) == sc) {
#pragma unroll
                for (int i = 0; i < 8; i++)
#pragma unroll
                    for (int j = 0; j < 8; j++)
                        Ts[(tx & 7)*8 + j][(ty & 7)*8 + i] = ov[i][j];
            }
            __syncthreads();
            for (int e = tid; e < 64*32; e += 256) {
                int r = e >> 5, c2 = (e & 31) * 2;
                float2 v = *(float2*)&Ts[r][c2];
                *(float2*)&db[(size_t)(m0 + sc*64 + r)*NPTS + n0 + sr*64 + c2] = v;
            }
        }
}

// ---------------- top-k=20: global tournament, nodemin-seeded, 2 rows/warp ----------------
// Lane owns groups [lane*4, lane*4+4); group g covers cols [g*8, g*8+8) of dist.
// nm loaded from precomputed nodemin; candidate lane fetches the 8-leaf group
// from global dist (L2) and invalidates the extracted leaf in place (same thread
// always owns a group -> program-order RAW is safe; dist/nodemin are fully
// rewritten by the next dist_kernel, keeping graph replays deterministic).
// redux.min.s32 on the global column index gives exact lowest-index ties.
__global__ __launch_bounds__(256) void topk_kernel(float* __restrict__ dist,
                                                   const float* __restrict__ nodemin,
                                                   int* __restrict__ idx) {
    int tid = threadIdx.x;
    int warp = tid >> 5, lane = tid & 31;
    int b = blockIdx.y;
    int n = blockIdx.x * 16 + warp * 2;           // two rows per warp
    float* r0 = dist + ((size_t)b*NPTS + n)*NPTS;
    float* r1 = r0 + NPTS;
    float4 t0 = *(const float4*)(nodemin + ((size_t)b*NPTS + n)*128 + lane*4);
    float4 t1 = *(const float4*)(nodemin + ((size_t)b*NPTS + n + 1)*128 + lane*4);
    float nm0[4] = {t0.x, t0.y, t0.z, t0.w};
    float nm1[4] = {t1.x, t1.y, t1.z, t1.w};
    int* out0 = idx + ((size_t)b*NPTS + n)*KNN;
    int* out1 = out0 + KNN;
    for (int kk = 0; kk < KNN; kk++) {
        float lm0 = fminf(fminf(nm0[0], nm0[1]), fminf(nm0[2], nm0[3]));
        float lm1 = fminf(fminf(nm1[0], nm1[1]), fminf(nm1[2], nm1[3]));
        unsigned bu0 = __float_as_uint(lm0);
        unsigned bu1 = __float_as_uint(lm1);
        unsigned tu0 = bu0 ^ (((unsigned)((int)bu0 >> 31)) | 0x80000000u);
        unsigned tu1 = bu1 ^ (((unsigned)((int)bu1 >> 31)) | 0x80000000u);
        unsigned gm0 = redux_min_u32(tu0);
        unsigned gm1 = redux_min_u32(tu1);
        int mym0 = 0x7FFFFFFF, mym1 = 0x7FFFFFFF;
        int g0 = 0, g1 = 0, li0 = 0, li1 = 0;
        float v0[8], v1[8];
        if (tu0 == gm0) {
            g0 = (nm0[0]==lm0) ? 0 : (nm0[1]==lm0) ? 1 : (nm0[2]==lm0) ? 2 : 3;
            int grp = lane*4 + g0;
            const float4* p = (const float4*)(r0 + grp*8);
            float4 a = p[0], c = p[1];
            v0[0]=a.x; v0[1]=a.y; v0[2]=a.z; v0[3]=a.w;
            v0[4]=c.x; v0[5]=c.y; v0[6]=c.z; v0[7]=c.w;
            li0 = 7;
#pragma unroll
            for (int i = 6; i >= 0; i--) if (v0[i] == lm0) li0 = i;   // lowest i
            mym0 = grp*8 + li0;
        }
        if (tu1 == gm1) {
            g1 = (nm1[0]==lm1) ? 0 : (nm1[1]==lm1) ? 1 : (nm1[2]==lm1) ? 2 : 3;
            int grp = lane*4 + g1;
            const float4* p = (const float4*)(r1 + grp*8);
            float4 a = p[0], c = p[1];
            v1[0]=a.x; v1[1]=a.y; v1[2]=a.z; v1[3]=a.w;
            v1[4]=c.x; v1[5]=c.y; v1[6]=c.z; v1[7]=c.w;
            li1 = 7;
#pragma unroll
            for (int i = 6; i >= 0; i--) if (v1[i] == lm1) li1 = i;
            mym1 = grp*8 + li1;
        }
        int w0 = redux_min_s32(mym0);
        int w1 = redux_min_s32(mym1);
        if (mym0 == w0) {
            out0[kk] = w0;
            r0[w0] = 3.4e38f;
#pragma unroll
            for (int i = 0; i < 8; i++) if (i == li0) v0[i] = 3.4e38f;
            float m2 = fminf(fminf(fminf(v0[0],v0[1]), fminf(v0[2],v0[3])),
                             fminf(fminf(v0[4],v0[5]), fminf(v0[6],v0[7])));
#pragma unroll
            for (int g = 0; g < 4; g++) if (g == g0) nm0[g] = m2;
        }
        if (mym1 == w1) {
            out1[kk] = w1;
            r1[w1] = 3.4e38f;
#pragma unroll
            for (int i = 0; i < 8; i++) if (i == li1) v1[i] = 3.4e38f;
            float m2 = fminf(fminf(fminf(v1[0],v1[1]), fminf(v1[2],v1[3])),
                             fminf(fminf(v1[4],v1[5]), fminf(v1[6],v1[7])));
#pragma unroll
            for (int g = 0; g < 4; g++) if (g == g1) nm1[g] = m2;
        }
    }
}

// ---------------- u = h W1^T, w = h (W2-W1)^T  (f32x2-tiled) ----------------
template<int C, int O>
__global__ __launch_bounds__(256) void gemm_kernel(const float* __restrict__ h,
                                                   const float* __restrict__ W,
                                                   float* __restrict__ u,
                                                   float* __restrict__ w) {
    constexpr int KC = (C >= 8) ? 8 : 4;
    __shared__ float As[KC][144];
    __shared__ float B1[KC][72];
    __shared__ float B2[KC][72];
    int o0 = blockIdx.x * 64;
    int r0 = blockIdx.y * 64;
    int tid = threadIdx.x, tx = tid & 15, ty = tid >> 4;
    ull au[4][2], aw[4][2];
#pragma unroll
    for (int i = 0; i < 4; i++) { au[i][0]=0ull; au[i][1]=0ull; aw[i][0]=0ull; aw[i][1]=0ull; }
    for (int kk = 0; kk < C; kk += KC) {
#pragma unroll
        for (int t = 0; t < (64*KC)/256; t++) {
            int e = tid + t*256;
            int r = e / KC, c = e % KC;
            float va = h[(size_t)(r0 + r)*C + kk + c];
            *(float2*)&As[c][2*r] = make_float2(va, va);
            float w1 = W[(size_t)(o0 + r)*(2*C) + kk + c];
            float w2 = W[(size_t)(o0 + r)*(2*C) + C + kk + c];
            B1[c][r] = w1;
            B2[c][r] = w2 - w1;
        }
        __syncthreads();
#pragma unroll
        for (int c = 0; c < KC; c++) {
            ull a0 = *(const ull*)&As[c][(ty*4+0)*2];
            ull a1 = *(const ull*)&As[c][(ty*4+1)*2];
            ull a2 = *(const ull*)&As[c][(ty*4+2)*2];
            ull a3 = *(const ull*)&As[c][(ty*4+3)*2];
            ull p0 = *(const ull*)&B1[c][tx*4];
            ull p1 = *(const ull*)&B1[c][tx*4+2];
            ull q0 = *(const ull*)&B2[c][tx*4];
            ull q1 = *(const ull*)&B2[c][tx*4+2];
            fma2(au[0][0],a0,p0); fma2(au[0][1],a0,p1);
            fma2(au[1][0],a1,p0); fma2(au[1][1],a1,p1);
            fma2(au[2][0],a2,p0); fma2(au[2][1],a2,p1);
            fma2(au[3][0],a3,p0); fma2(au[3][1],a3,p1);
            fma2(aw[0][0],a0,q0); fma2(aw[0][1],a0,q1);
            fma2(aw[1][0],a1,q0); fma2(aw[1][1],a1,q1);
            fma2(aw[2][0],a2,q0); fma2(aw[2][1],a2,q1);
            fma2(aw[3][0],a3,q0); fma2(aw[3][1],a3,q1);
        }
        __syncthreads();
    }
#pragma unroll
    for (int i = 0; i < 4; i++) {
        float2 u0 = upk(au[i][0]), u1 = upk(au[i][1]);
        float2 v0 = upk(aw[i][0]), v1 = upk(aw[i][1]);
        size_t off = (size_t)(r0 + ty*4 + i)*O + o0 + tx*4;
        *(float4*)&u[off] = make_float4(u0.x, u0.y, u1.x, u1.y);
        *(float4*)&w[off] = make_float4(v0.x, v0.y, v1.x, v1.y);
    }
}

// ---------------- single gather pass: sums, sumsq, per-(n,o) ymax/ymin ----------------
template<int O>
__global__ void stats_kernel(const float* __restrict__ u, const float* __restrict__ w,
                             const int* __restrict__ idx,
                             float* __restrict__ ps, float* __restrict__ pq,
                             float* __restrict__ ymax, float* __restrict__ ymin) {
    __shared__ int idxs[16*KNN];
    int blk = blockIdx.x;
    int node0 = blk * 16;
    int o = threadIdx.x;
    for (int e = threadIdx.x; e < 16*KNN; e += O) idxs[e] = idx[(size_t)node0*KNN + e];
    __syncthreads();
    const float* ub = u + (size_t)(node0 & ~(NPTS-1))*O;   // batch base
    float s = 0.f, q = 0.f;
    for (int n = 0; n < 16; n++) {
        float wv = w[(size_t)(node0 + n)*O + o];
        float mx = -3.4e38f, mn = 3.4e38f;
#pragma unroll
        for (int kk = 0; kk < KNN; kk++) {
            float y = ub[(size_t)idxs[n*KNN + kk]*O + o] + wv;
            s += y; q += y*y;
            mx = fmaxf(mx, y); mn = fminf(mn, y);
        }
        ymax[(size_t)(node0 + n)*O + o] = mx;
        ymin[(size_t)(node0 + n)*O + o] = mn;
    }
    ps[(size_t)o*1024 + blk] = s;
    pq[(size_t)o*1024 + blk] = q;
}

// ---------------- reduce partials -> scale/shift per channel ----------------
__global__ void bnstats_kernel(const float* __restrict__ ps, const float* __restrict__ pq,
                               const float* __restrict__ g, const float* __restrict__ bt,
                               float* __restrict__ scale, float* __restrict__ shift) {
    int o = blockIdx.x*8 + (threadIdx.x >> 5);
    int lane = threadIdx.x & 31;
    float s = 0.f, q = 0.f;
    for (int p = lane; p < 1024; p += 32) { s += ps[(size_t)o*1024 + p]; q += pq[(size_t)o*1024 + p]; }
#pragma unroll
    for (int off = 16; off; off >>= 1) {
        s += __shfl_down_sync(0xffffffffu, s, off);
        q += __shfl_down_sync(0xffffffffu, q, off);
    }
    if (lane == 0) {
        const float inv = 1.f / (float)(BATCH*NPTS*KNN);
        float mean = s * inv;
        float var  = q * inv - mean*mean;
        float rs   = rsqrtf(var + 1e-5f);
        float sc   = g[o] * rs;
        scale[o] = sc;
        shift[o] = bt[o] - mean*sc;
    }
}

// ---------------- finalize: BN + LeakyReLU on the k-extremum (monotone trick) ----------------
template<int O>
__global__ void finalize_kernel(const float* __restrict__ ymax, const float* __restrict__ ymin,
                                const float* __restrict__ scale, const float* __restrict__ shift,
                                float* __restrict__ hout) {
    int i = blockIdx.x*256 + threadIdx.x;           // over BN*O
    int o = i & (O-1);
    float sc = scale[o];
    float y  = (sc >= 0.f) ? ymax[i] : ymin[i];
    float v  = y*sc + shift[o];
    hout[i] = (v >= 0.f) ? v : 0.2f*v;
}

// ---------------- final max over N (two deterministic stages) ----------------
__global__ void pmax_kernel(const float* __restrict__ h, float* __restrict__ part) {
    int b = blockIdx.y, ch = blockIdx.x, o = threadIdx.x;
    const float* hp = h + ((size_t)b*NPTS + ch*64)*256 + o;
    float m = -3.4e38f;
    for (int n = 0; n < 64; n++) m = fmaxf(m, hp[(size_t)n*256]);
    part[((size_t)b*16 + ch)*256 + o] = m;
}
__global__ void fmax_kernel(const float* __restrict__ part, float* __restrict__ out) {
    int b = blockIdx.x, o = threadIdx.x;
    float m = -3.4e38f;
    for (int c = 0; c < 16; c++) m = fmaxf(m, part[((size_t)b*16 + c)*256 + o]);
    out[(size_t)b*256 + o] = m;
}

// ---------------- host orchestration ----------------
struct Scratch {
    float *hA, *hB, *u, *w, *ymax, *ymin, *xx, *dist, *nodemin, *ps, *pq, *scale, *shift, *part;
    int* idx;
};

template<int C, int O>
static void run_layer(const float* hin, float* hout, const float* W,
                      const float* g, const float* bt, const Scratch& Z) {
    xx_kernel<C><<<BN/256, 256>>>(hin, Z.xx);
    dist_kernel<C><<<dim3(8, 8, BATCH), 256>>>(hin, Z.xx, Z.dist, Z.nodemin);
    topk_kernel<<<dim3(NPTS/16, BATCH), 256>>>(Z.dist, Z.nodemin, Z.idx);
    gemm_kernel<C, O><<<dim3(O/64, BN/64), 256>>>(hin, W, Z.u, Z.w);
    stats_kernel<O><<<BN/16, O>>>(Z.u, Z.w, Z.idx, Z.ps, Z.pq, Z.ymax, Z.ymin);
    bnstats_kernel<<<O/8, 256>>>(Z.ps, Z.pq, g, bt, Z.scale, Z.shift);
    finalize_kernel<O><<<(BN*O)/256, 256>>>(Z.ymax, Z.ymin, Z.scale, Z.shift, hout);
}

extern "C" void kernel_launch(void* const* d_in, const int* in_sizes, int n_in,
                              void* d_out, int out_size) {
    const float* x = (const float*)d_in[0];
    const float* Wp[4]; const float* gp[4]; const float* bp[4];
    for (int i = 0; i < 4; i++) {
        Wp[i] = (const float*)d_in[1 + 3*i];
        gp[i] = (const float*)d_in[2 + 3*i];
        bp[i] = (const float*)d_in[3 + 3*i];
    }
    Scratch Z;
    cudaGetSymbolAddress((void**)&Z.hA,      g_hA);
    cudaGetSymbolAddress((void**)&Z.hB,      g_hB);
    cudaGetSymbolAddress((void**)&Z.u,       g_u);
    cudaGetSymbolAddress((void**)&Z.w,       g_w);
    cudaGetSymbolAddress((void**)&Z.ymax,    g_ymax);
    cudaGetSymbolAddress((void**)&Z.ymin,    g_ymin);
    cudaGetSymbolAddress((void**)&Z.xx,      g_xx);
    cudaGetSymbolAddress((void**)&Z.dist,    g_dist);
    cudaGetSymbolAddress((void**)&Z.nodemin, g_nodemin);
    cudaGetSymbolAddress((void**)&Z.ps,      g_ps);
    cudaGetSymbolAddress((void**)&Z.pq,      g_pq);
    cudaGetSymbolAddress((void**)&Z.scale,   g_scale);
    cudaGetSymbolAddress((void**)&Z.shift,   g_shift);
    cudaGetSymbolAddress((void**)&Z.part,    g_part);
    cudaGetSymbolAddress((void**)&Z.idx,     g_idx);

    prep_kernel<<<(BN*4)/256, 256>>>(x, Z.hA);

    run_layer<4,   64 >(Z.hA, Z.hB, Wp[0], gp[0], bp[0], Z);
    run_layer<64,  64 >(Z.hB, Z.hA, Wp[1], gp[1], bp[1], Z);
    run_layer<64,  128>(Z.hA, Z.hB, Wp[2], gp[2], bp[2], Z);
    run_layer<128, 256>(Z.hB, Z.hA, Wp[3], gp[3], bp[3], Z);

    pmax_kernel<<<dim3(16, BATCH), 256>>>(Z.hA, Z.part);
    fmax_kernel<<<BATCH, 256>>>(Z.part, (float*)d_out);
}

// round 7
// speedup vs baseline: 1.0852x; 1.0852x over previous
#include <cuda_runtime.h>
#include <cstddef>

#define BATCH 16
#define NPTS  1024
#define KNN   20
#define BN    (BATCH*NPTS)

typedef unsigned long long ull;

// ---------------- scratch (static device globals; allocation-free) ----------------
__device__ float g_hA[BN*256];
__device__ float g_hB[BN*256];
__device__ float g_u [BN*256];
__device__ float g_w [BN*256];
__device__ float g_ymax[BN*256];
__device__ float g_ymin[BN*256];
__device__ float g_xx[BN];
__device__ float g_dist[BATCH*NPTS*NPTS];     // 67 MB, L2-resident
__device__ float g_nodemin[BN*128];           // per-row mins of contiguous 8-col groups
__device__ int   g_idx[BN*KNN];
__device__ float g_ps[262144];                // stats partials [o][P], O*P == 262144
__device__ float g_pq[262144];
__device__ float g_scale[256];
__device__ float g_shift[256];
__device__ float g_part[BATCH*16*256];

// ---------------- f32x2 helpers ----------------
__device__ __forceinline__ void fma2(ull& d, ull a, ull b) {
    asm("fma.rn.f32x2 %0, %1, %2, %0;" : "+l"(d) : "l"(a), "l"(b));
}
__device__ __forceinline__ float2 upk(ull v) {
    float2 f; asm("mov.b64 {%0,%1}, %2;" : "=f"(f.x), "=f"(f.y) : "l"(v)); return f;
}
__device__ __forceinline__ unsigned redux_min_u32(unsigned v) {
    unsigned r; asm("redux.sync.min.u32 %0, %1, 0xffffffff;" : "=r"(r) : "r"(v)); return r;
}
__device__ __forceinline__ int redux_min_s32(int v) {
    int r; asm("redux.sync.min.s32 %0, %1, 0xffffffff;" : "=r"(r) : "r"(v)); return r;
}

// ---------------- prep: x (B,1,4,N) -> h (B,N,4) ----------------
__global__ void prep_kernel(const float* __restrict__ x, float* __restrict__ h) {
    int i = blockIdx.x*256 + threadIdx.x;          // over B*N*4
    int c = i & 3, n = (i >> 2) & (NPTS-1), b = i >> 12;
    h[i] = x[((size_t)b*4 + c)*NPTS + n];
}

// ---------------- xx[b,n] = |h_bn|^2 ----------------
template<int C>
__global__ void xx_kernel(const float* __restrict__ h, float* __restrict__ xx) {
    int i = blockIdx.x*256 + threadIdx.x;          // over B*N
    const float4* hp = (const float4*)(h + (size_t)i*C);
    float s = 0.f;
#pragma unroll
    for (int c = 0; c < C/4; c++) { float4 v = hp[c]; s += v.x*v.x + v.y*v.y + v.z*v.z + v.w*v.w; }
    xx[i] = s;
}

// ---------------- pairwise squared distances + per-group node mins ----------------
template<int C>
__global__ __launch_bounds__(256) void dist_kernel(const float* __restrict__ h,
                                                   const float* __restrict__ xx,
                                                   float* __restrict__ dist,
                                                   float* __restrict__ nodemin) {
    constexpr int KC = (C >= 8) ? 8 : 4;
    __shared__ float As[KC][264];   // 128 rows duplicated pairs (256 floats) + pad
    __shared__ float Bs[KC][136];   // 128 floats + pad
    __shared__ float Ts[64][66];    // transpose staging (float2-aligned dump)
    int bx = blockIdx.x, by = blockIdx.y, b = blockIdx.z;
    if (bx > by) return;            // symmetry: compute lower triangle, mirror
    int n0 = by * 128, m0 = bx * 128;
    int tid = threadIdx.x;
    int tx = tid & 15, ty = tid >> 4;   // 16x16 threads, 8x8 values each
    ull acc[8][4];
#pragma unroll
    for (int i = 0; i < 8; i++)
#pragma unroll
        for (int j = 0; j < 4; j++) acc[i][j] = 0ull;
    const float* hb = h + (size_t)b*NPTS*C;
    for (int kk = 0; kk < C; kk += KC) {
        for (int e = tid; e < 128*KC; e += 256) {
            int r = e / KC, c = e % KC;
            float va = hb[(size_t)(n0 + r)*C + kk + c];
            As[c][2*r] = va; As[c][2*r+1] = va;
            Bs[c][r] = hb[(size_t)(m0 + r)*C + kk + c];
        }
        __syncthreads();
#pragma unroll
        for (int c = 0; c < KC; c++) {
            const ull* ap = (const ull*)&As[c][ty*16];
            const ull* bp = (const ull*)&Bs[c][tx*8];
            ull A[8], B[4];
#pragma unroll
            for (int i = 0; i < 8; i++) A[i] = ap[i];
#pragma unroll
            for (int j = 0; j < 4; j++) B[j] = bp[j];
#pragma unroll
            for (int i = 0; i < 8; i++)
#pragma unroll
                for (int j = 0; j < 4; j++) fma2(acc[i][j], A[i], B[j]);
        }
        __syncthreads();
    }
    const float* xxb = xx + b*NPTS;
    float xn[8], xm[8];
#pragma unroll
    for (int i = 0; i < 8; i++) { xn[i] = xxb[n0+ty*8+i]; xm[i] = xxb[m0+tx*8+i]; }
    float ov[8][8];
#pragma unroll
    for (int i = 0; i < 8; i++)
#pragma unroll
        for (int j = 0; j < 4; j++) {
            float2 p = upk(acc[i][j]);
            ov[i][2*j]   = xn[i] + xm[2*j]   - 2.f*p.x;
            ov[i][2*j+1] = xn[i] + xm[2*j+1] - 2.f*p.y;
        }
    float* db = dist + (size_t)b*NPTS*NPTS;
    float* nmb = nodemin + (size_t)b*NPTS*128;
#pragma unroll
    for (int i = 0; i < 8; i++) {
        size_t off = (size_t)(n0+ty*8+i)*NPTS + m0 + tx*8;
        *(float4*)&db[off]   = make_float4(ov[i][0], ov[i][1], ov[i][2], ov[i][3]);
        *(float4*)&db[off+4] = make_float4(ov[i][4], ov[i][5], ov[i][6], ov[i][7]);
        // node min for row n0+ty*8+i, group bx*16+tx (cols m0+tx*8..+7)
        float m = fminf(fminf(fminf(ov[i][0],ov[i][1]), fminf(ov[i][2],ov[i][3])),
                        fminf(fminf(ov[i][4],ov[i][5]), fminf(ov[i][6],ov[i][7])));
        nmb[(size_t)(n0+ty*8+i)*128 + bx*16 + tx] = m;
    }
    if (bx == by) return;
    // mirror node mins: row m0+tx*8+j, group by*16+ty (cols n0+ty*8..+7)
#pragma unroll
    for (int j = 0; j < 8; j++) {
        float m = fminf(fminf(fminf(ov[0][j],ov[1][j]), fminf(ov[2][j],ov[3][j])),
                        fminf(fminf(ov[4][j],ov[5][j]), fminf(ov[6][j],ov[7][j])));
        nmb[(size_t)(m0+tx*8+j)*128 + by*16 + ty] = m;
    }
    // mirror dist: 4 sub-passes through a 64x64 smem transpose
#pragma unroll
    for (int sr = 0; sr < 2; sr++)
#pragma unroll
        for (int sc = 0; sc < 2; sc++) {
            __syncthreads();
            if ((ty >> 3) == sr && (tx >> 3) == sc) {
#pragma unroll
                for (int i = 0; i < 8; i++)
#pragma unroll
                    for (int j = 0; j < 8; j++)
                        Ts[(tx & 7)*8 + j][(ty & 7)*8 + i] = ov[i][j];
            }
            __syncthreads();
            for (int e = tid; e < 64*32; e += 256) {
                int r = e >> 5, c2 = (e & 31) * 2;
                float2 v = *(float2*)&Ts[r][c2];
                *(float2*)&db[(size_t)(m0 + sc*64 + r)*NPTS + n0 + sr*64 + c2] = v;
            }
        }
}

// ---------------- top-k=20: smem tournament seeded by precomputed node mins ----------------
// Warp per row; row staged in smem. Lane owns contiguous groups [lane*4, lane*4+4),
// group grp covers cols [grp*8, grp*8+8). nm[4] loaded from nodemin (built in dist).
// Per round: lane-min (3 fmin) -> redux.min.u32 on order-mapped bits -> candidate
// lane(s) locate lowest index in their group (2 LDS.128) -> redux.min.s32 exact
// lowest-index tie-break -> unique winner writes out, invalidates smem leaf,
// recomputes its nm[g]. Set semantics match jax.lax.top_k.
__global__ __launch_bounds__(256) void topk_kernel(const float* __restrict__ dist,
                                                   const float* __restrict__ nodemin,
                                                   int* __restrict__ idx) {
    __shared__ float ds[8][NPTS];
    int b = blockIdx.y, n0 = blockIdx.x * 8;
    int tid = threadIdx.x;
    const float4* src = (const float4*)(dist + ((size_t)b*NPTS + n0)*NPTS);
    float4* dst = (float4*)&ds[0][0];
    for (int e = tid; e < 8*256; e += 256) dst[e] = src[e];
    __syncthreads();
    int wr = tid >> 5, lane = tid & 31;
    float* rowf = ds[wr];
    float4 t = *(const float4*)(nodemin + ((size_t)b*NPTS + n0 + wr)*128 + lane*4);
    float nm[4] = {t.x, t.y, t.z, t.w};
    int* out = idx + ((size_t)b*NPTS + n0 + wr)*KNN;
    for (int kk = 0; kk < KNN; kk++) {
        float lm = fminf(fminf(nm[0], nm[1]), fminf(nm[2], nm[3]));
        unsigned bu = __float_as_uint(lm);
        unsigned tu = bu ^ (((unsigned)((int)bu >> 31)) | 0x80000000u);
        unsigned gm = redux_min_u32(tu);
        int mym = 0x7FFFFFFF;
        int g = 0, li = 0;
        float v[8];
        if (tu == gm) {
            g = (nm[0]==lm) ? 0 : (nm[1]==lm) ? 1 : (nm[2]==lm) ? 2 : 3;
            int grp = lane*4 + g;
            const float4* p = (const float4*)&rowf[grp*8];
            float4 a = p[0], c = p[1];
            v[0]=a.x; v[1]=a.y; v[2]=a.z; v[3]=a.w;
            v[4]=c.x; v[5]=c.y; v[6]=c.z; v[7]=c.w;
            li = 7;
#pragma unroll
            for (int i = 6; i >= 0; i--) if (v[i] == lm) li = i;   // lowest i
            mym = grp*8 + li;
        }
        int mwin = redux_min_s32(mym);            // lowest global col among ties
        if (mym == mwin) {
            out[kk] = mwin;
            rowf[mwin] = 3.4e38f;
#pragma unroll
            for (int i = 0; i < 8; i++) if (i == li) v[i] = 3.4e38f;
            float m2 = fminf(fminf(fminf(v[0],v[1]), fminf(v[2],v[3])),
                             fminf(fminf(v[4],v[5]), fminf(v[6],v[7])));
#pragma unroll
            for (int g2 = 0; g2 < 4; g2++) if (g2 == g) nm[g2] = m2;
        }
    }
}

// ---------------- u = h W1^T, w = h (W2-W1)^T  (f32x2-tiled) ----------------
template<int C, int O>
__global__ __launch_bounds__(256) void gemm_kernel(const float* __restrict__ h,
                                                   const float* __restrict__ W,
                                                   float* __restrict__ u,
                                                   float* __restrict__ w) {
    constexpr int KC = (C >= 8) ? 8 : 4;
    __shared__ float As[KC][144];
    __shared__ float B1[KC][72];
    __shared__ float B2[KC][72];
    int o0 = blockIdx.x * 64;
    int r0 = blockIdx.y * 64;
    int tid = threadIdx.x, tx = tid & 15, ty = tid >> 4;
    ull au[4][2], aw[4][2];
#pragma unroll
    for (int i = 0; i < 4; i++) { au[i][0]=0ull; au[i][1]=0ull; aw[i][0]=0ull; aw[i][1]=0ull; }
    for (int kk = 0; kk < C; kk += KC) {
#pragma unroll
        for (int t = 0; t < (64*KC)/256; t++) {
            int e = tid + t*256;
            int r = e / KC, c = e % KC;
            float va = h[(size_t)(r0 + r)*C + kk + c];
            *(float2*)&As[c][2*r] = make_float2(va, va);
            float w1 = W[(size_t)(o0 + r)*(2*C) + kk + c];
            float w2 = W[(size_t)(o0 + r)*(2*C) + C + kk + c];
            B1[c][r] = w1;
            B2[c][r] = w2 - w1;
        }
        __syncthreads();
#pragma unroll
        for (int c = 0; c < KC; c++) {
            ull a0 = *(const ull*)&As[c][(ty*4+0)*2];
            ull a1 = *(const ull*)&As[c][(ty*4+1)*2];
            ull a2 = *(const ull*)&As[c][(ty*4+2)*2];
            ull a3 = *(const ull*)&As[c][(ty*4+3)*2];
            ull p0 = *(const ull*)&B1[c][tx*4];
            ull p1 = *(const ull*)&B1[c][tx*4+2];
            ull q0 = *(const ull*)&B2[c][tx*4];
            ull q1 = *(const ull*)&B2[c][tx*4+2];
            fma2(au[0][0],a0,p0); fma2(au[0][1],a0,p1);
            fma2(au[1][0],a1,p0); fma2(au[1][1],a1,p1);
            fma2(au[2][0],a2,p0); fma2(au[2][1],a2,p1);
            fma2(au[3][0],a3,p0); fma2(au[3][1],a3,p1);
            fma2(aw[0][0],a0,q0); fma2(aw[0][1],a0,q1);
            fma2(aw[1][0],a1,q0); fma2(aw[1][1],a1,q1);
            fma2(aw[2][0],a2,q0); fma2(aw[2][1],a2,q1);
            fma2(aw[3][0],a3,q0); fma2(aw[3][1],a3,q1);
        }
        __syncthreads();
    }
#pragma unroll
    for (int i = 0; i < 4; i++) {
        float2 u0 = upk(au[i][0]), u1 = upk(au[i][1]);
        float2 v0 = upk(aw[i][0]), v1 = upk(aw[i][1]);
        size_t off = (size_t)(r0 + ty*4 + i)*O + o0 + tx*4;
        *(float4*)&u[off] = make_float4(u0.x, u0.y, u1.x, u1.y);
        *(float4*)&w[off] = make_float4(v0.x, v0.y, v1.x, v1.y);
    }
}

// ---------------- gather pass: float4-vectorized sums/sumsq + per-(n,o) ymax/ymin ----------------
// Block = 256 threads = (O/4 channel-groups) x (NL node-lanes); 64 nodes per block.
template<int O>
__global__ __launch_bounds__(256) void stats_kernel(const float* __restrict__ u,
                                                    const float* __restrict__ w,
                                                    const int* __restrict__ idx,
                                                    float* __restrict__ ps, float* __restrict__ pq,
                                                    float* __restrict__ ymax, float* __restrict__ ymin,
                                                    int P) {
    constexpr int C4 = O/4;            // channel groups of 4
    constexpr int NL = 256/C4;         // node lanes
    __shared__ int idxs[64*KNN];
    int blk = blockIdx.x, node0 = blk * 64;
    int tid = threadIdx.x;
    int c4 = tid % C4, nl = tid / C4;
    for (int e = tid; e < 64*KNN; e += 256) idxs[e] = idx[(size_t)node0*KNN + e];
    __syncthreads();
    const float4* ub = (const float4*)(u + (size_t)(node0 & ~(NPTS-1))*O);   // batch base
    float s0=0.f,s1=0.f,s2=0.f,s3=0.f,q0=0.f,q1=0.f,q2=0.f,q3=0.f;
    for (int ni = nl; ni < 64; ni += NL) {
        int n = node0 + ni;
        float4 wv = *(const float4*)(w + (size_t)n*O + c4*4);
        float4 mx = make_float4(-3.4e38f,-3.4e38f,-3.4e38f,-3.4e38f);
        float4 mn = make_float4( 3.4e38f, 3.4e38f, 3.4e38f, 3.4e38f);
#pragma unroll
        for (int k = 0; k < KNN; k++) {
            int r = idxs[ni*KNN + k];
            float4 y = ub[(size_t)r*C4 + c4];
            y.x += wv.x; y.y += wv.y; y.z += wv.z; y.w += wv.w;
            s0 += y.x; q0 += y.x*y.x; mx.x = fmaxf(mx.x,y.x); mn.x = fminf(mn.x,y.x);
            s1 += y.y; q1 += y.y*y.y; mx.y = fmaxf(mx.y,y.y); mn.y = fminf(mn.y,y.y);
            s2 += y.z; q2 += y.z*y.z; mx.z = fmaxf(mx.z,y.z); mn.z = fminf(mn.z,y.z);
            s3 += y.w; q3 += y.w*y.w; mx.w = fmaxf(mx.w,y.w); mn.w = fminf(mn.w,y.w);
        }
        *(float4*)(ymax + (size_t)n*O + c4*4) = mx;
        *(float4*)(ymin + (size_t)n*O + c4*4) = mn;
    }
    int col = blk*NL + nl;
    ps[(size_t)(c4*4+0)*P + col] = s0;  pq[(size_t)(c4*4+0)*P + col] = q0;
    ps[(size_t)(c4*4+1)*P + col] = s1;  pq[(size_t)(c4*4+1)*P + col] = q1;
    ps[(size_t)(c4*4+2)*P + col] = s2;  pq[(size_t)(c4*4+2)*P + col] = q2;
    ps[(size_t)(c4*4+3)*P + col] = s3;  pq[(size_t)(c4*4+3)*P + col] = q3;
}

// ---------------- reduce partials -> scale/shift per channel ----------------
__global__ void bnstats_kernel(const float* __restrict__ ps, const float* __restrict__ pq,
                               const float* __restrict__ g, const float* __restrict__ bt,
                               float* __restrict__ scale, float* __restrict__ shift, int P) {
    int o = blockIdx.x*8 + (threadIdx.x >> 5);
    int lane = threadIdx.x & 31;
    float s = 0.f, q = 0.f;
    for (int p = lane; p < P; p += 32) { s += ps[(size_t)o*P + p]; q += pq[(size_t)o*P + p]; }
#pragma unroll
    for (int off = 16; off; off >>= 1) {
        s += __shfl_down_sync(0xffffffffu, s, off);
        q += __shfl_down_sync(0xffffffffu, q, off);
    }
    if (lane == 0) {
        const float inv = 1.f / (float)(BATCH*NPTS*KNN);
        float mean = s * inv;
        float var  = q * inv - mean*mean;
        float rs   = rsqrtf(var + 1e-5f);
        float sc   = g[o] * rs;
        scale[o] = sc;
        shift[o] = bt[o] - mean*sc;
    }
}

// ---------------- finalize: BN + LeakyReLU on the k-extremum (monotone trick) ----------------
template<int O>
__global__ void finalize_kernel(const float* __restrict__ ymax, const float* __restrict__ ymin,
                                const float* __restrict__ scale, const float* __restrict__ shift,
                                float* __restrict__ hout) {
    int i = blockIdx.x*256 + threadIdx.x;           // over BN*O
    int o = i & (O-1);
    float sc = scale[o];
    float y  = (sc >= 0.f) ? ymax[i] : ymin[i];
    float v  = y*sc + shift[o];
    hout[i] = (v >= 0.f) ? v : 0.2f*v;
}

// ---------------- final max over N (two deterministic stages) ----------------
__global__ void pmax_kernel(const float* __restrict__ h, float* __restrict__ part) {
    int b = blockIdx.y, ch = blockIdx.x, o = threadIdx.x;
    const float* hp = h + ((size_t)b*NPTS + ch*64)*256 + o;
    float m = -3.4e38f;
    for (int n = 0; n < 64; n++) m = fmaxf(m, hp[(size_t)n*256]);
    part[((size_t)b*16 + ch)*256 + o] = m;
}
__global__ void fmax_kernel(const float* __restrict__ part, float* __restrict__ out) {
    int b = blockIdx.x, o = threadIdx.x;
    float m = -3.4e38f;
    for (int c = 0; c < 16; c++) m = fmaxf(m, part[((size_t)b*16 + c)*256 + o]);
    out[(size_t)b*256 + o] = m;
}

// ---------------- host orchestration ----------------
struct Scratch {
    float *hA, *hB, *u, *w, *ymax, *ymin, *xx, *dist, *nodemin, *ps, *pq, *scale, *shift, *part;
    int* idx;
};

template<int C, int O>
static void run_layer(const float* hin, float* hout, const float* W,
                      const float* g, const float* bt, const Scratch& Z) {
    int P = 262144 / O;
    xx_kernel<C><<<BN/256, 256>>>(hin, Z.xx);
    dist_kernel<C><<<dim3(8, 8, BATCH), 256>>>(hin, Z.xx, Z.dist, Z.nodemin);
    topk_kernel<<<dim3(NPTS/8, BATCH), 256>>>(Z.dist, Z.nodemin, Z.idx);
    gemm_kernel<C, O><<<dim3(O/64, BN/64), 256>>>(hin, W, Z.u, Z.w);
    stats_kernel<O><<<BN/64, 256>>>(Z.u, Z.w, Z.idx, Z.ps, Z.pq, Z.ymax, Z.ymin, P);
    bnstats_kernel<<<O/8, 256>>>(Z.ps, Z.pq, g, bt, Z.scale, Z.shift, P);
    finalize_kernel<O><<<(BN*O)/256, 256>>>(Z.ymax, Z.ymin, Z.scale, Z.shift, hout);
}

extern "C" void kernel_launch(void* const* d_in, const int* in_sizes, int n_in,
                              void* d_out, int out_size) {
    const float* x = (const float*)d_in[0];
    const float* Wp[4]; const float* gp[4]; const float* bp[4];
    for (int i = 0; i < 4; i++) {
        Wp[i] = (const float*)d_in[1 + 3*i];
        gp[i] = (const float*)d_in[2 + 3*i];
        bp[i] = (const float*)d_in[3 + 3*i];
    }
    Scratch Z;
    cudaGetSymbolAddress((void**)&Z.hA,      g_hA);
    cudaGetSymbolAddress((void**)&Z.hB,      g_hB);
    cudaGetSymbolAddress((void**)&Z.u,       g_u);
    cudaGetSymbolAddress((void**)&Z.w,       g_w);
    cudaGetSymbolAddress((void**)&Z.ymax,    g_ymax);
    cudaGetSymbolAddress((void**)&Z.ymin,    g_ymin);
    cudaGetSymbolAddress((void**)&Z.xx,      g_xx);
    cudaGetSymbolAddress((void**)&Z.dist,    g_dist);
    cudaGetSymbolAddress((void**)&Z.nodemin, g_nodemin);
    cudaGetSymbolAddress((void**)&Z.ps,      g_ps);
    cudaGetSymbolAddress((void**)&Z.pq,      g_pq);
    cudaGetSymbolAddress((void**)&Z.scale,   g_scale);
    cudaGetSymbolAddress((void**)&Z.shift,   g_shift);
    cudaGetSymbolAddress((void**)&Z.part,    g_part);
    cudaGetSymbolAddress((void**)&Z.idx,     g_idx);

    prep_kernel<<<(BN*4)/256, 256>>>(x, Z.hA);

    run_layer<4,   64 >(Z.hA, Z.hB, Wp[0], gp[0], bp[0], Z);
    run_layer<64,  64 >(Z.hB, Z.hA, Wp[1], gp[1], bp[1], Z);
    run_layer<64,  128>(Z.hA, Z.hB, Wp[2], gp[2], bp[2], Z);
    run_layer<128, 256>(Z.hB, Z.hA, Wp[3], gp[3], bp[3], Z);

    pmax_kernel<<<dim3(16, BATCH), 256>>>(Z.hA, Z.part);
    fmax_kernel<<<BATCH, 256>>>(Z.part, (float*)d_out);
}